// round 4
// baseline (speedup 1.0000x reference)
#include <cuda_runtime.h>
#include <cuda_bf16.h>
#include <cstdint>

// HashGridEncoding, R4: spatial bucket-sort of points (32^3 linear cell id)
// + level-major warps (warp w = level w, lanes = 32 consecutive sorted
// points). Sorted lanes share table sectors at low/mid levels and share
// cache lines at high levels -> fewer L1 gather sectors + less DRAM.

#define NUM_LEVELS 9
#define PMAX 262144
#define NB   32768           // 32^3 buckets (level-5 resolution)

__device__ int g_hist[NB];
__device__ int g_off[NB];
__device__ int g_bucket[PMAX];
__device__ int g_sorted[PMAX];

// ---------- pass 0: zero histogram ----------
__global__ void k_zero()
{
    int i = blockIdx.x * blockDim.x + threadIdx.x;
    if (i < NB) g_hist[i] = 0;
}

// ---------- pass 1: bucket id + histogram ----------
__global__ void k_hist(const float* __restrict__ x, int P)
{
    int p = blockIdx.x * blockDim.x + threadIdx.x;
    if (p >= P) return;
    float nx = (x[p * 3 + 0] + 1.0f) * 0.5f;
    float ny = (x[p * 3 + 1] + 1.0f) * 0.5f;
    float nz = (x[p * 3 + 2] + 1.0f) * 0.5f;
    int cx = min(31, max(0, (int)(nx * 32.0f)));
    int cy = min(31, max(0, (int)(ny * 32.0f)));
    int cz = min(31, max(0, (int)(nz * 32.0f)));
    int b = cx + (cy << 5) + (cz << 10);
    g_bucket[p] = b;
    atomicAdd(&g_hist[b], 1);
}

// ---------- pass 2: exclusive scan of 32768 counters (single block) ----------
__global__ void __launch_bounds__(1024) k_scan()
{
    __shared__ int s[1024];
    int t = threadIdx.x;
    int base = t * 32;
    int loc[32];
    int sum = 0;
#pragma unroll
    for (int i = 0; i < 32; i++) { loc[i] = g_hist[base + i]; sum += loc[i]; }
    s[t] = sum;
    __syncthreads();
    // Hillis-Steele inclusive scan
    for (int off = 1; off < 1024; off <<= 1) {
        int v = (t >= off) ? s[t - off] : 0;
        __syncthreads();
        s[t] += v;
        __syncthreads();
    }
    int run = (t == 0) ? 0 : s[t - 1];
#pragma unroll
    for (int i = 0; i < 32; i++) { g_off[base + i] = run; run += loc[i]; }
}

// ---------- pass 3: scatter point ids into sorted order ----------
__global__ void k_scatter(int P)
{
    int p = blockIdx.x * blockDim.x + threadIdx.x;
    if (p >= P) return;
    int b = g_bucket[p];
    int pos = atomicAdd(&g_off[b], 1);
    g_sorted[pos] = p;
}

// ---------- pass 4: main interpolation ----------
__global__ void __launch_bounds__(288) k_main(
    const float* __restrict__ x,
    const float* __restrict__ table,
    float* __restrict__ out,
    int P)
{
    __shared__ float  spx[32], spy[32], spz[32];
    __shared__ int    sidx[32];
    __shared__ float2 sres[32][NUM_LEVELS];

    int pbase = blockIdx.x * 32;
    int t = threadIdx.x;

    if (t < 32) {
        int gp = pbase + t;
        int op = (gp < P) ? g_sorted[gp] : 0;
        sidx[t] = op;
        spx[t] = x[op * 3 + 0];
        spy[t] = x[op * 3 + 1];
        spz[t] = x[op * 3 + 2];
    }
    __syncthreads();

    int w    = t >> 5;          // warp id == level (9 warps)
    int lane = t & 31;          // lane == sorted point within block

    {
        int   vi = 1 << w;
        float vf = (float)vi;

        float gx = (spx[lane] + 1.0f) * 0.5f * vf;
        float gy = (spy[lane] + 1.0f) * 0.5f * vf;
        float gz = (spz[lane] + 1.0f) * 0.5f * vf;

        float bxf = floorf(gx);
        float byf = floorf(gy);
        float bzf = floorf(gz);

        float fx = gx - bxf;
        float fy = gy - byf;
        float fz = gz - bzf;

        int ix = (int)bxf;
        int iy = (int)byf;
        int iz = (int)bzf;

        int flat = ix + iy * vi + iz * vi * vi;
        int dz   = vi * vi;

        const float2* __restrict__ tab = (const float2*)table;

        float2 q000 = __ldg(tab + flat);
        float2 q100 = __ldg(tab + flat + 1);
        float2 q010 = __ldg(tab + flat + vi);
        float2 q110 = __ldg(tab + flat + vi + 1);
        float2 q001 = __ldg(tab + flat + dz);
        float2 q101 = __ldg(tab + flat + dz + 1);
        float2 q011 = __ldg(tab + flat + dz + vi);
        float2 q111 = __ldg(tab + flat + dz + vi + 1);

        float wx0 = 1.0f - fx, wx1 = fx;
        float wy0 = 1.0f - fy, wy1 = fy;
        float wz0 = 1.0f - fz, wz1 = fz;

        float a0x = wx0 * q000.x + wx1 * q100.x;
        float a0y = wx0 * q000.y + wx1 * q100.y;
        float a1x = wx0 * q010.x + wx1 * q110.x;
        float a1y = wx0 * q010.y + wx1 * q110.y;
        float a2x = wx0 * q001.x + wx1 * q101.x;
        float a2y = wx0 * q001.y + wx1 * q101.y;
        float a3x = wx0 * q011.x + wx1 * q111.x;
        float a3y = wx0 * q011.y + wx1 * q111.y;

        float b0x = wy0 * a0x + wy1 * a1x;
        float b0y = wy0 * a0y + wy1 * a1y;
        float b1x = wy0 * a2x + wy1 * a3x;
        float b1y = wy0 * a2y + wy1 * a3y;

        sres[lane][w] = make_float2(wz0 * b0x + wz1 * b1x,
                                    wz0 * b0y + wz1 * b1y);
    }
    __syncthreads();

    // write-out: thread t -> point t/9, level t%9; 9-thread groups write
    // 72B contiguous at out[orig_p].
    int pi = t / NUM_LEVELS;
    int li = t - pi * NUM_LEVELS;
    if (pbase + pi < P) {
        float2* __restrict__ o2 = (float2*)out;
        o2[sidx[pi] * NUM_LEVELS + li] = sres[pi][li];
    }
}

extern "C" void kernel_launch(void* const* d_in, const int* in_sizes, int n_in,
                              void* d_out, int out_size)
{
    const float* x     = (const float*)d_in[0];
    const float* table = (const float*)d_in[1];
    float* out         = (float*)d_out;

    int P = in_sizes[0] / 3;
    if (P > PMAX) P = PMAX;

    k_zero<<<(NB + 255) / 256, 256>>>();
    k_hist<<<(P + 255) / 256, 256>>>(x, P);
    k_scan<<<1, 1024>>>();
    k_scatter<<<(P + 255) / 256, 256>>>(P);
    k_main<<<(P + 31) / 32, 288>>>(x, table, out, P);
}

// round 5
// speedup vs baseline: 1.3295x; 1.3295x over previous
#include <cuda_runtime.h>
#include <cuda_bf16.h>
#include <cstdint>

// HashGridEncoding R5: spatial bucket sort (32^3 cells, avg 8 pts/bucket) with
// CHEAP passes + level-major sorted main kernel with pair-merged LDG.128.
// Model: runtime ~ L1 gather wavefronts; sorting makes warp lanes spatially
// coherent -> shared lines at l<=6, line-pair merge halves l7/l8.

#define NUM_LEVELS 9
#define PMAX 262144
#define NB   32768           // 32^3 buckets

__device__ int   g_hist[NB];
__device__ int   g_off[NB];
__device__ int   g_bucket[PMAX];
__device__ int   g_sorted[PMAX];
__device__ float g_xs[PMAX * 3];   // x re-gathered into sorted order

// ---------- pass 0: zero histogram ----------
__global__ void k_zero()
{
    int i = blockIdx.x * blockDim.x + threadIdx.x;
    if (i < NB / 4) ((int4*)g_hist)[i] = make_int4(0, 0, 0, 0);
}

// ---------- pass 1: bucket id + histogram ----------
__global__ void k_hist(const float* __restrict__ x, int P)
{
    int p = blockIdx.x * blockDim.x + threadIdx.x;
    if (p >= P) return;
    float nx = (x[p * 3 + 0] + 1.0f) * 0.5f;
    float ny = (x[p * 3 + 1] + 1.0f) * 0.5f;
    float nz = (x[p * 3 + 2] + 1.0f) * 0.5f;
    int cx = min(31, max(0, (int)(nx * 32.0f)));
    int cy = min(31, max(0, (int)(ny * 32.0f)));
    int cz = min(31, max(0, (int)(nz * 32.0f)));
    int b = cx + (cy << 5) + (cz << 10);
    g_bucket[p] = b;
    atomicAdd(&g_hist[b], 1);
}

// ---------- pass 2: exclusive scan, 1 block, shuffle-based (3 barriers) ----
__global__ void __launch_bounds__(1024) k_scan()
{
    int t = threadIdx.x, lane = t & 31, wid = t >> 5;
    const int4* __restrict__ h4 = (const int4*)g_hist;
    int4 v[8];
    int base4 = t * 8;
#pragma unroll
    for (int i = 0; i < 8; i++) v[i] = h4[base4 + i];
    int sum = 0;
#pragma unroll
    for (int i = 0; i < 8; i++) sum += v[i].x + v[i].y + v[i].z + v[i].w;

    // warp inclusive scan of per-thread sums
    int inc = sum;
#pragma unroll
    for (int off = 1; off < 32; off <<= 1) {
        int n = __shfl_up_sync(0xFFFFFFFFu, inc, off);
        if (lane >= off) inc += n;
    }
    __shared__ int woff[32];
    if (lane == 31) woff[wid] = inc;
    __syncthreads();
    if (wid == 0) {
        int wv = woff[lane];
        int winc = wv;
#pragma unroll
        for (int off = 1; off < 32; off <<= 1) {
            int n = __shfl_up_sync(0xFFFFFFFFu, winc, off);
            if (lane >= off) winc += n;
        }
        woff[lane] = winc - wv;   // exclusive
    }
    __syncthreads();

    int run = woff[wid] + (inc - sum);
    int4* __restrict__ o4 = (int4*)g_off;
#pragma unroll
    for (int i = 0; i < 8; i++) {
        int4 w;
        w.x = run; run += v[i].x;
        w.y = run; run += v[i].y;
        w.z = run; run += v[i].z;
        w.w = run; run += v[i].w;
        o4[base4 + i] = w;
    }
}

// ---------- pass 3: scatter ids + re-gather x into sorted order ----------
__global__ void k_scatter(const float* __restrict__ x, int P)
{
    int p = blockIdx.x * blockDim.x + threadIdx.x;
    if (p >= P) return;
    float x0 = x[p * 3 + 0];
    float x1 = x[p * 3 + 1];
    float x2 = x[p * 3 + 2];
    int b = g_bucket[p];
    int pos = atomicAdd(&g_off[b], 1);
    g_sorted[pos] = p;
    g_xs[pos * 3 + 0] = x0;
    g_xs[pos * 3 + 1] = x1;
    g_xs[pos * 3 + 2] = x2;
}

// ---------- aligned float4 pair load: (q[b], q[b+1]) ----------
__device__ __forceinline__ void load_pair(const float4* __restrict__ t4, int b,
                                          float2& q0, float2& q1)
{
    int a = b >> 1;
    float4 qa = __ldg(t4 + a);
    if (b & 1) {
        float4 qb = __ldg(t4 + a + 1);
        q0 = make_float2(qa.z, qa.w);
        q1 = make_float2(qb.x, qb.y);
    } else {
        q0 = make_float2(qa.x, qa.y);
        q1 = make_float2(qa.z, qa.w);
    }
}

// ---------- pass 4: main, level-major warps over sorted points ----------
__global__ void __launch_bounds__(288) k_main(
    const float* __restrict__ table,
    float* __restrict__ out,
    int P)
{
    __shared__ float  sx[96];                // 32 sorted points x 3 (coalesced)
    __shared__ int    sidx[32];
    __shared__ float2 sres[32][NUM_LEVELS];

    int pbase = blockIdx.x * 32;
    int t = threadIdx.x;

    if (t < 96) {
        int g = pbase * 3 + t;
        sx[t] = (g < P * 3) ? g_xs[g] : 0.0f;
    }
    if (t >= 96 && t < 128) {
        int gp = pbase + (t - 96);
        sidx[t - 96] = (gp < P) ? g_sorted[gp] : 0;
    }
    __syncthreads();

    int w    = t >> 5;          // warp id == level
    int lane = t & 31;          // lane == sorted point within block

    {
        int   vi = 1 << w;
        float vf = (float)vi;

        float gx = (sx[lane * 3 + 0] + 1.0f) * 0.5f * vf;
        float gy = (sx[lane * 3 + 1] + 1.0f) * 0.5f * vf;
        float gz = (sx[lane * 3 + 2] + 1.0f) * 0.5f * vf;

        float bxf = floorf(gx);
        float byf = floorf(gy);
        float bzf = floorf(gz);

        float fx = gx - bxf;
        float fy = gy - byf;
        float fz = gz - bzf;

        int ix = (int)bxf;
        int iy = (int)byf;
        int iz = (int)bzf;

        int flat = ix + iy * vi + iz * vi * vi;
        int dz   = vi * vi;

        const float4* __restrict__ tab4 = (const float4*)table;

        float2 q000, q100, q010, q110, q001, q101, q011, q111;
        load_pair(tab4, flat,           q000, q100);
        load_pair(tab4, flat + vi,      q010, q110);
        load_pair(tab4, flat + dz,      q001, q101);
        load_pair(tab4, flat + dz + vi, q011, q111);

        float wx0 = 1.0f - fx, wx1 = fx;
        float wy0 = 1.0f - fy, wy1 = fy;
        float wz0 = 1.0f - fz, wz1 = fz;

        float a0x = wx0 * q000.x + wx1 * q100.x;
        float a0y = wx0 * q000.y + wx1 * q100.y;
        float a1x = wx0 * q010.x + wx1 * q110.x;
        float a1y = wx0 * q010.y + wx1 * q110.y;
        float a2x = wx0 * q001.x + wx1 * q101.x;
        float a2y = wx0 * q001.y + wx1 * q101.y;
        float a3x = wx0 * q011.x + wx1 * q111.x;
        float a3y = wx0 * q011.y + wx1 * q111.y;

        float b0x = wy0 * a0x + wy1 * a1x;
        float b0y = wy0 * a0y + wy1 * a1y;
        float b1x = wy0 * a2x + wy1 * a3x;
        float b1y = wy0 * a2y + wy1 * a3y;

        sres[lane][w] = make_float2(wz0 * b0x + wz1 * b1x,
                                    wz0 * b0y + wz1 * b1y);
    }
    __syncthreads();

    // write-out: thread t -> point t/9, level t%9 (9 threads = 72B contiguous)
    int pi = t / NUM_LEVELS;
    int li = t - pi * NUM_LEVELS;
    if (pbase + pi < P) {
        float2* __restrict__ o2 = (float2*)out;
        o2[sidx[pi] * NUM_LEVELS + li] = sres[pi][li];
    }
}

extern "C" void kernel_launch(void* const* d_in, const int* in_sizes, int n_in,
                              void* d_out, int out_size)
{
    const float* x     = (const float*)d_in[0];
    const float* table = (const float*)d_in[1];
    float* out         = (float*)d_out;

    int P = in_sizes[0] / 3;
    if (P > PMAX) P = PMAX;

    k_zero<<<(NB / 4 + 255) / 256, 256>>>();
    k_hist<<<(P + 255) / 256, 256>>>(x, P);
    k_scan<<<1, 1024>>>();
    k_scatter<<<(P + 255) / 256, 256>>>(x, P);
    k_main<<<(P + 31) / 32, 288>>>(table, out, P);
}

// round 6
// speedup vs baseline: 1.4415x; 1.0842x over previous
#include <cuda_runtime.h>
#include <cuda_bf16.h>
#include <cstdint>

// HashGridEncoding R6: spatial bucket sort + level-major sorted main kernel.
// R5 confirmed sorted k_main < 13us (was 37 unsorted); this round kills the
// sort overhead: rank computed in hist pass (atomic return), scatter is
// atomic-free with ONE scattered float4 store {x,y,z,id}.

#define NUM_LEVELS 9
#define PMAX 262144
#define NB   32768           // 32^3 buckets

__device__ int    g_hist[NB];
__device__ int    g_off[NB];      // exclusive scan (immutable after k_scan)
__device__ int    g_bucket[PMAX];
__device__ int    g_rank[PMAX];
__device__ float4 g_xs4[PMAX];    // sorted {x, y, z, bitcast(orig_id)}

// ---------- pass 0: zero histogram ----------
__global__ void k_zero()
{
    int i = blockIdx.x * blockDim.x + threadIdx.x;
    if (i < NB / 4) ((int4*)g_hist)[i] = make_int4(0, 0, 0, 0);
}

// ---------- pass 1: bucket id + histogram; atomic return = rank ----------
__global__ void k_hist(const float* __restrict__ x, int P)
{
    int p = blockIdx.x * blockDim.x + threadIdx.x;
    if (p >= P) return;
    float nx = (x[p * 3 + 0] + 1.0f) * 0.5f;
    float ny = (x[p * 3 + 1] + 1.0f) * 0.5f;
    float nz = (x[p * 3 + 2] + 1.0f) * 0.5f;
    int cx = min(31, max(0, (int)(nx * 32.0f)));
    int cy = min(31, max(0, (int)(ny * 32.0f)));
    int cz = min(31, max(0, (int)(nz * 32.0f)));
    int b = cx + (cy << 5) + (cz << 10);
    g_bucket[p] = b;
    g_rank[p] = atomicAdd(&g_hist[b], 1);
}

// ---------- pass 2: exclusive scan, 1 block, shuffle-based ----------
__global__ void __launch_bounds__(1024) k_scan()
{
    int t = threadIdx.x, lane = t & 31, wid = t >> 5;
    const int4* __restrict__ h4 = (const int4*)g_hist;
    int4 v[8];
    int base4 = t * 8;
#pragma unroll
    for (int i = 0; i < 8; i++) v[i] = h4[base4 + i];
    int sum = 0;
#pragma unroll
    for (int i = 0; i < 8; i++) sum += v[i].x + v[i].y + v[i].z + v[i].w;

    int inc = sum;
#pragma unroll
    for (int off = 1; off < 32; off <<= 1) {
        int n = __shfl_up_sync(0xFFFFFFFFu, inc, off);
        if (lane >= off) inc += n;
    }
    __shared__ int woff[32];
    if (lane == 31) woff[wid] = inc;
    __syncthreads();
    if (wid == 0) {
        int wv = woff[lane];
        int winc = wv;
#pragma unroll
        for (int off = 1; off < 32; off <<= 1) {
            int n = __shfl_up_sync(0xFFFFFFFFu, winc, off);
            if (lane >= off) winc += n;
        }
        woff[lane] = winc - wv;   // exclusive
    }
    __syncthreads();

    int run = woff[wid] + (inc - sum);
    int4* __restrict__ o4 = (int4*)g_off;
#pragma unroll
    for (int i = 0; i < 8; i++) {
        int4 w;
        w.x = run; run += v[i].x;
        w.y = run; run += v[i].y;
        w.z = run; run += v[i].z;
        w.w = run; run += v[i].w;
        o4[base4 + i] = w;
    }
}

// ---------- pass 3: atomic-free scatter, single float4 store ----------
__global__ void k_scatter(const float* __restrict__ x, int P)
{
    int p = blockIdx.x * blockDim.x + threadIdx.x;
    if (p >= P) return;
    float x0 = x[p * 3 + 0];
    float x1 = x[p * 3 + 1];
    float x2 = x[p * 3 + 2];
    int b = g_bucket[p];
    int r = g_rank[p];
    int pos = g_off[b] + r;
    g_xs4[pos] = make_float4(x0, x1, x2, __int_as_float(p));
}

// ---------- aligned float4 pair load: (q[b], q[b+1]) ----------
__device__ __forceinline__ void load_pair(const float4* __restrict__ t4, int b,
                                          float2& q0, float2& q1)
{
    int a = b >> 1;
    float4 qa = __ldg(t4 + a);
    if (b & 1) {
        float4 qb = __ldg(t4 + a + 1);
        q0 = make_float2(qa.z, qa.w);
        q1 = make_float2(qb.x, qb.y);
    } else {
        q0 = make_float2(qa.x, qa.y);
        q1 = make_float2(qa.z, qa.w);
    }
}

// ---------- pass 4: main, level-major warps over sorted points ----------
__global__ void __launch_bounds__(288) k_main(
    const float* __restrict__ table,
    float* __restrict__ out,
    int P)
{
    __shared__ float  spx[32], spy[32], spz[32];
    __shared__ int    sidx[32];
    __shared__ float2 sres[32][NUM_LEVELS];

    int pbase = blockIdx.x * 32;
    int t = threadIdx.x;

    if (t < 32) {
        int gp = pbase + t;
        float4 f = (gp < P) ? g_xs4[gp] : make_float4(0.f, 0.f, 0.f, 0.f);
        spx[t] = f.x; spy[t] = f.y; spz[t] = f.z;
        sidx[t] = __float_as_int(f.w);
    }
    __syncthreads();

    int w    = t >> 5;          // warp id == level
    int lane = t & 31;          // lane == sorted point within block

    {
        int   vi = 1 << w;
        float vf = (float)vi;

        float gx = (spx[lane] + 1.0f) * 0.5f * vf;
        float gy = (spy[lane] + 1.0f) * 0.5f * vf;
        float gz = (spz[lane] + 1.0f) * 0.5f * vf;

        float bxf = floorf(gx);
        float byf = floorf(gy);
        float bzf = floorf(gz);

        float fx = gx - bxf;
        float fy = gy - byf;
        float fz = gz - bzf;

        int ix = (int)bxf;
        int iy = (int)byf;
        int iz = (int)bzf;

        int flat = ix + iy * vi + iz * vi * vi;
        int dz   = vi * vi;

        const float4* __restrict__ tab4 = (const float4*)table;

        float2 q000, q100, q010, q110, q001, q101, q011, q111;
        load_pair(tab4, flat,           q000, q100);
        load_pair(tab4, flat + vi,      q010, q110);
        load_pair(tab4, flat + dz,      q001, q101);
        load_pair(tab4, flat + dz + vi, q011, q111);

        float wx0 = 1.0f - fx, wx1 = fx;
        float wy0 = 1.0f - fy, wy1 = fy;
        float wz0 = 1.0f - fz, wz1 = fz;

        float a0x = wx0 * q000.x + wx1 * q100.x;
        float a0y = wx0 * q000.y + wx1 * q100.y;
        float a1x = wx0 * q010.x + wx1 * q110.x;
        float a1y = wx0 * q010.y + wx1 * q110.y;
        float a2x = wx0 * q001.x + wx1 * q101.x;
        float a2y = wx0 * q001.y + wx1 * q101.y;
        float a3x = wx0 * q011.x + wx1 * q111.x;
        float a3y = wx0 * q011.y + wx1 * q111.y;

        float b0x = wy0 * a0x + wy1 * a1x;
        float b0y = wy0 * a0y + wy1 * a1y;
        float b1x = wy0 * a2x + wy1 * a3x;
        float b1y = wy0 * a2y + wy1 * a3y;

        sres[lane][w] = make_float2(wz0 * b0x + wz1 * b1x,
                                    wz0 * b0y + wz1 * b1y);
    }
    __syncthreads();

    // write-out: thread t -> point t/9, level t%9 (9 threads = 72B contiguous)
    int pi = t / NUM_LEVELS;
    int li = t - pi * NUM_LEVELS;
    if (pbase + pi < P) {
        float2* __restrict__ o2 = (float2*)out;
        o2[sidx[pi] * NUM_LEVELS + li] = sres[pi][li];
    }
}

extern "C" void kernel_launch(void* const* d_in, const int* in_sizes, int n_in,
                              void* d_out, int out_size)
{
    const float* x     = (const float*)d_in[0];
    const float* table = (const float*)d_in[1];
    float* out         = (float*)d_out;

    int P = in_sizes[0] / 3;
    if (P > PMAX) P = PMAX;

    k_zero<<<(NB / 4 + 255) / 256, 256>>>();
    k_hist<<<(P + 255) / 256, 256>>>(x, P);
    k_scan<<<1, 1024>>>();
    k_scatter<<<(P + 255) / 256, 256>>>(x, P);
    k_main<<<(P + 31) / 32, 288>>>(table, out, P);
}